// round 2
// baseline (speedup 1.0000x reference)
#include <cuda_runtime.h>

// ---------------------------------------------------------------------------
// Forecaster_PONI round 2: register-blocked, vectorized fp32 convs with
// split-K (deterministic partial buffers + epilogue kernels) for occupancy.
// ---------------------------------------------------------------------------

__device__ __forceinline__ float lrelu_f(float v) { return v > 0.f ? v : 0.2f * v; }
__device__ __forceinline__ float sigm_f(float v)  { return 1.f / (1.f + __expf(-v)); }

// ------------------------------ scratch buffers ----------------------------
__device__ float g_e1[160 * 16 * 96 * 96];
__device__ float g_e2[160 * 64 * 48 * 48];
__device__ float g_e3[160 * 96 * 24 * 24];
__device__ float g_c3[2][16 * 96 * 24 * 24];
__device__ float g_c2[2][16 * 64 * 48 * 48];
__device__ float g_c1[2][16 * 16 * 96 * 96];
__device__ float g_g3[16 * 192 * 24 * 24];
__device__ float g_g2[16 * 128 * 48 * 48];
__device__ float g_g1[16 * 32 * 96 * 96];
__device__ float g_o3[16 * 64 * 48 * 48];
__device__ float g_o2[16 * 16 * 96 * 96];
__device__ float g_o1[16 * 8 * 192 * 192];
// split-K partial accumulators (max user: L2 gate = 2*16*128*48*48 floats)
__device__ float g_part[2 * 16 * 128 * 48 * 48];

static const int NB = 16;  // batch

// ---------------------------------------------------------------------------
// conv3x3 v2: stride-1 SAME conv over [x1 (C1) ++ x2 (C2)].
// Thread computes PXR rows x 4 cols of output, COT output channels.
// MODE 1 = gate conv (plain concat). MODE 2 = candidate (x2 scaled by r from
// gates on load; SPLIT==1 epilogue does GRU combine).
// SPLIT>1: raw partial sums written to part[sp] (no bias/act).
// ACT (SPLIT==1 only): 1 lrelu, 2 sigmoid.
// ---------------------------------------------------------------------------
template<int C1, int C2, int CO, int H, int W, int ACT, int MODE,
         int TY, int TX, int PXR, int CICH, int COT, int SPLIT>
__global__ void __launch_bounds__((TY / PXR) * (TX / 4))
conv3x3_v2(const float* __restrict__ x1, const float* __restrict__ x2,
           const float* __restrict__ gates, const float* __restrict__ wgt,
           const float* __restrict__ bias, float* __restrict__ out)
{
    constexpr int CI  = C1 + C2;
    constexpr int CIP = CI / SPLIT;
    constexpr int SH  = TY + 2, SW = TX + 2, SWP = (SW + 3) & ~3;
    constexpr int NT  = (TY / PXR) * (TX / 4);
    constexpr int TILES_X = W / TX;

    __shared__ __align__(16) float s_in[CICH][SH][SWP];
    __shared__ __align__(16) float s_w[CICH][COT][12];

    const int zs  = blockIdx.z;
    const int n   = zs / SPLIT;
    const int sp  = zs % SPLIT;
    const int cob = blockIdx.y * COT;
    const int ty0 = (blockIdx.x / TILES_X) * TY;
    const int tx0 = (blockIdx.x % TILES_X) * TX;
    const int tid = threadIdx.x;
    const int lx  = tid % (TX / 4);
    const int ly  = tid / (TX / 4);

    float acc[COT][PXR][4];
#pragma unroll
    for (int c = 0; c < COT; c++)
#pragma unroll
        for (int r = 0; r < PXR; r++)
#pragma unroll
            for (int j = 0; j < 4; j++) acc[c][r][j] = 0.f;

    const int ci_base = sp * CIP;
    for (int ci0 = 0; ci0 < CIP; ci0 += CICH) {
        for (int idx = tid; idx < CICH * SH * SW; idx += NT) {
            int c   = idx / (SH * SW);
            int rem = idx - c * (SH * SW);
            int iy  = rem / SW;
            int ix  = rem - iy * SW;
            int gy = ty0 + iy - 1, gx = tx0 + ix - 1;
            int ci = ci_base + ci0 + c;
            float v = 0.f;
            if ((unsigned)gy < (unsigned)H && (unsigned)gx < (unsigned)W) {
                if (ci < C1) {
                    v = x1[((n * C1 + ci) * H + gy) * W + gx];
                } else {
                    int c2 = ci - C1;
                    v = x2[((n * C2 + c2) * H + gy) * W + gx];
                    if (MODE == 2)
                        v *= gates[((n * 2 * C2 + C2 + c2) * H + gy) * W + gx];
                }
            }
            s_in[c][iy][ix] = v;
        }
        for (int idx = tid; idx < CICH * COT * 9; idx += NT) {
            int c   = idx / (COT * 9);
            int rem = idx - c * (COT * 9);
            int co  = rem / 9;
            int k   = rem - co * 9;
            s_w[c][co][k] = wgt[((cob + co) * CI + (ci_base + ci0 + c)) * 9 + k];
        }
        __syncthreads();

#pragma unroll
        for (int c = 0; c < CICH; c++) {
            float p[PXR + 2][6];
#pragma unroll
            for (int r = 0; r < PXR + 2; r++) {
                float4 q  = *(const float4*)&s_in[c][PXR * ly + r][4 * lx];
                float2 q2 = *(const float2*)&s_in[c][PXR * ly + r][4 * lx + 4];
                p[r][0] = q.x; p[r][1] = q.y; p[r][2] = q.z; p[r][3] = q.w;
                p[r][4] = q2.x; p[r][5] = q2.y;
            }
#pragma unroll
            for (int co = 0; co < COT; co++) {
                float4 w0 = *(const float4*)&s_w[c][co][0];
                float4 w1 = *(const float4*)&s_w[c][co][4];
                float  w8 = s_w[c][co][8];
                float wk[9] = {w0.x, w0.y, w0.z, w0.w, w1.x, w1.y, w1.z, w1.w, w8};
#pragma unroll
                for (int ky = 0; ky < 3; ky++)
#pragma unroll
                    for (int kx = 0; kx < 3; kx++)
#pragma unroll
                        for (int r = 0; r < PXR; r++)
#pragma unroll
                            for (int cc = 0; cc < 4; cc++)
                                acc[co][r][cc] = fmaf(p[r + ky][cc + kx],
                                                      wk[ky * 3 + kx],
                                                      acc[co][r][cc]);
            }
        }
        __syncthreads();
    }

    const int oy = ty0 + PXR * ly, ox = tx0 + 4 * lx;
    if (SPLIT > 1) {
#pragma unroll
        for (int co = 0; co < COT; co++)
#pragma unroll
            for (int r = 0; r < PXR; r++) {
                float4 v = {acc[co][r][0], acc[co][r][1], acc[co][r][2], acc[co][r][3]};
                *(float4*)&out[(((size_t)(sp * NB + n) * CO + cob + co) * H + oy + r) * W + ox] = v;
            }
    } else {
#pragma unroll
        for (int co = 0; co < COT; co++) {
            float bv = bias[cob + co];
#pragma unroll
            for (int r = 0; r < PXR; r++) {
                int y = oy + r;
                float v[4];
#pragma unroll
                for (int cc = 0; cc < 4; cc++) {
                    float t = acc[co][r][cc] + bv;
                    if (ACT == 1) t = lrelu_f(t);
                    if (ACT == 2) t = sigm_f(t);
                    v[cc] = t;
                }
                size_t off = (((size_t)n * CO + cob + co) * H + y) * W + ox;
                if (MODE == 2) {
                    float4 z4 = *(const float4*)&gates[(((size_t)n * 2 * CO + cob + co) * H + y) * W + ox];
                    float4 h4 = *(const float4*)&x2[off];
                    v[0] = (1.f - z4.x) * h4.x + z4.x * v[0];
                    v[1] = (1.f - z4.y) * h4.y + z4.y * v[1];
                    v[2] = (1.f - z4.z) * h4.z + z4.z * v[2];
                    v[3] = (1.f - z4.w) * h4.w + z4.w * v[3];
                }
                float4 o = {v[0], v[1], v[2], v[3]};
                *(float4*)&out[off] = o;
            }
        }
    }
}

// ---------------------------------------------------------------------------
// deconv v2: 4x4 stride-2 SAME transposed conv (unflipped kernel).
// Thread owns 2x2 input pixels -> 4x4 outputs, COT channels.
// FUSE: 1 -> lrelu(acc+b) in-kernel; 0 -> raw partial write (SPLIT>1).
// ---------------------------------------------------------------------------
template<int CI, int CO, int HIN, int TY, int TX, int CICH, int COT, int SPLIT, int FUSE>
__global__ void __launch_bounds__((TY / 2) * (TX / 2))
deconv_v2(const float* __restrict__ x, const float* __restrict__ wgt,
          const float* __restrict__ bias, float* __restrict__ out)
{
    constexpr int WIN = HIN, HO = 2 * HIN, WO = 2 * HIN;
    constexpr int CIP = CI / SPLIT;
    constexpr int SH  = TY + 2, SW = TX + 2, SWP = (SW + 3) & ~3;
    constexpr int NT  = (TY / 2) * (TX / 2);
    constexpr int TILES_X = WIN / TX;

    __shared__ __align__(16) float s_in[CICH][SH][SWP];
    __shared__ __align__(16) float s_w[CICH][COT][16];

    const int zs  = blockIdx.z;
    const int n   = zs / SPLIT;
    const int sp  = zs % SPLIT;
    const int cob = blockIdx.y * COT;
    const int ty0 = (blockIdx.x / TILES_X) * TY;
    const int tx0 = (blockIdx.x % TILES_X) * TX;
    const int tid = threadIdx.x;
    const int lx  = tid % (TX / 2);
    const int ly  = tid / (TX / 2);

    float acc[COT][4][4];
#pragma unroll
    for (int c = 0; c < COT; c++)
#pragma unroll
        for (int u = 0; u < 4; u++)
#pragma unroll
            for (int v = 0; v < 4; v++) acc[c][u][v] = 0.f;

    const int ci_base = sp * CIP;
    for (int ci0 = 0; ci0 < CIP; ci0 += CICH) {
        for (int idx = tid; idx < CICH * SH * SW; idx += NT) {
            int c   = idx / (SH * SW);
            int rem = idx - c * (SH * SW);
            int iy  = rem / SW;
            int ix  = rem - iy * SW;
            int gy = ty0 + iy - 1, gx = tx0 + ix - 1;
            float v = 0.f;
            if ((unsigned)gy < (unsigned)HIN && (unsigned)gx < (unsigned)WIN)
                v = x[(((size_t)n * CI + (ci_base + ci0 + c)) * HIN + gy) * WIN + gx];
            s_in[c][iy][ix] = v;
        }
        for (int idx = tid; idx < CICH * COT * 16; idx += NT) {
            int c   = idx / (COT * 16);
            int rem = idx - c * (COT * 16);
            int co  = rem / 16;
            int k   = rem - co * 16;
            s_w[c][co][k] = wgt[((cob + co) * CI + (ci_base + ci0 + c)) * 16 + k];
        }
        __syncthreads();

#pragma unroll
        for (int c = 0; c < CICH; c++) {
            float p[4][4];
#pragma unroll
            for (int r = 0; r < 4; r++) {
                float2 a = *(const float2*)&s_in[c][2 * ly + r][2 * lx];
                float2 b = *(const float2*)&s_in[c][2 * ly + r][2 * lx + 2];
                p[r][0] = a.x; p[r][1] = a.y; p[r][2] = b.x; p[r][3] = b.y;
            }
#pragma unroll
            for (int co = 0; co < COT; co++) {
                float wk[16];
#pragma unroll
                for (int q = 0; q < 4; q++) {
                    float4 wv = *(const float4*)&s_w[c][co][4 * q];
                    wk[4 * q] = wv.x; wk[4 * q + 1] = wv.y;
                    wk[4 * q + 2] = wv.z; wk[4 * q + 3] = wv.w;
                }
#pragma unroll
                for (int u = 0; u < 4; u++)
#pragma unroll
                    for (int v = 0; v < 4; v++)
#pragma unroll
                        for (int a = 0; a < 2; a++)
#pragma unroll
                            for (int b = 0; b < 2; b++)
                                acc[co][u][v] = fmaf(
                                    p[(u >> 1) + (u & 1) + a][(v >> 1) + (v & 1) + b],
                                    wk[((u & 1) + 2 * a) * 4 + (v & 1) + 2 * b],
                                    acc[co][u][v]);
            }
        }
        __syncthreads();
    }

    const int orow0 = 2 * ty0 + 4 * ly;
    const int ocol0 = 2 * tx0 + 4 * lx;
#pragma unroll
    for (int co = 0; co < COT; co++) {
        float bv = FUSE ? bias[cob + co] : 0.f;
#pragma unroll
        for (int u = 0; u < 4; u++) {
            float4 v;
            if (FUSE) {
                v.x = lrelu_f(acc[co][u][0] + bv);
                v.y = lrelu_f(acc[co][u][1] + bv);
                v.z = lrelu_f(acc[co][u][2] + bv);
                v.w = lrelu_f(acc[co][u][3] + bv);
                *(float4*)&out[(((size_t)n * CO + cob + co) * HO + orow0 + u) * WO + ocol0] = v;
            } else {
                v.x = acc[co][u][0]; v.y = acc[co][u][1];
                v.z = acc[co][u][2]; v.w = acc[co][u][3];
                *(float4*)&out[(((size_t)(sp * NB + n) * CO + cob + co) * HO + orow0 + u) * WO + ocol0] = v;
            }
        }
    }
}

// ---------------------------------------------------------------------------
// Epilogue: sum SPLIT partials + bias, then:
// MODE 0: lrelu        MODE 1: sigmoid
// MODE 2: GRU combine  out = (1-z)*h + z*lrelu(s)
// ---------------------------------------------------------------------------
template<int CO, int HW, int SPLIT, int MODE>
__global__ void epi_k(const float* __restrict__ part, const float* __restrict__ bias,
                      const float* __restrict__ gates, const float* __restrict__ hprev,
                      float* __restrict__ out)
{
    constexpr size_t TOT = (size_t)NB * CO * HW;
    size_t i = ((size_t)blockIdx.x * blockDim.x + threadIdx.x) * 4;
    if (i >= TOT) return;
    int c   = (int)((i / HW) % CO);
    float4 s = *(const float4*)&part[i];
#pragma unroll
    for (int sp = 1; sp < SPLIT; sp++) {
        float4 q = *(const float4*)&part[(size_t)sp * TOT + i];
        s.x += q.x; s.y += q.y; s.z += q.z; s.w += q.w;
    }
    float bv = bias[c];
    s.x += bv; s.y += bv; s.z += bv; s.w += bv;
    if (MODE == 0) {
        s.x = lrelu_f(s.x); s.y = lrelu_f(s.y); s.z = lrelu_f(s.z); s.w = lrelu_f(s.w);
    } else if (MODE == 1) {
        s.x = sigm_f(s.x); s.y = sigm_f(s.y); s.z = sigm_f(s.z); s.w = sigm_f(s.w);
    } else {
        int n   = (int)(i / ((size_t)HW * CO));
        size_t pix = i % HW;
        float4 z = *(const float4*)&gates[((size_t)(n * 2 * CO + c)) * HW + pix];
        float4 h = *(const float4*)&hprev[i];
        s.x = (1.f - z.x) * h.x + z.x * lrelu_f(s.x);
        s.y = (1.f - z.y) * h.y + z.y * lrelu_f(s.y);
        s.z = (1.f - z.z) * h.z + z.z * lrelu_f(s.z);
        s.w = (1.f - z.w) * h.w + z.w * lrelu_f(s.w);
    }
    *(float4*)&out[i] = s;
}

// ---------------------------------------------------------------------------
// Encoder: 3x3 stride-2 SAME conv (kept from round 1).
// ---------------------------------------------------------------------------
template<int CI, int CO, int HIN, bool REMAP, int TY, int TX, int CICH, int COT>
__global__ void __launch_bounds__(TY * TX)
conv3x3s2_k(const float* __restrict__ x, const float* __restrict__ wgt,
            const float* __restrict__ bias, float* __restrict__ out)
{
    constexpr int WIN = HIN, HO = HIN / 2, WO = HIN / 2;
    constexpr int SH = 2 * TY + 1, SW = 2 * TX + 1;
    constexpr int NT = TY * TX;
    constexpr int TILES_X = (WO + TX - 1) / TX;
    __shared__ float s_in[CICH][SH][SW];
    __shared__ float s_w[CICH][COT][9];

    const int n   = blockIdx.z;
    const int cob = blockIdx.y * COT;
    const int ty0 = (blockIdx.x / TILES_X) * TY;
    const int tx0 = (blockIdx.x % TILES_X) * TX;
    const int tid = threadIdx.x;
    const int lx  = tid % TX;
    const int ly  = tid / TX;

    float acc[COT];
#pragma unroll
    for (int c = 0; c < COT; c++) acc[c] = 0.f;

    for (int ci0 = 0; ci0 < CI; ci0 += CICH) {
        for (int idx = tid; idx < CICH * SH * SW; idx += NT) {
            int c   = idx / (SH * SW);
            int rem = idx - c * (SH * SW);
            int iy  = rem / SW;
            int ix  = rem - iy * SW;
            int gy = 2 * ty0 + iy, gx = 2 * tx0 + ix;
            int ci = ci0 + c;
            float v = 0.f;
            if (gy < HIN && gx < WIN) {
                int frame = REMAP ? ((n % 16) * 10 + n / 16) : n;
                v = x[(((size_t)frame * CI + ci) * HIN + gy) * WIN + gx];
            }
            s_in[c][iy][ix] = v;
        }
        for (int idx = tid; idx < CICH * COT * 9; idx += NT) {
            int c   = idx / (COT * 9);
            int rem = idx - c * (COT * 9);
            int co  = rem / 9;
            int k   = rem - co * 9;
            s_w[c][co][k] = wgt[((cob + co) * CI + (ci0 + c)) * 9 + k];
        }
        __syncthreads();

        for (int c = 0; c < CICH; c++) {
            float p[3][3];
#pragma unroll
            for (int r = 0; r < 3; r++)
#pragma unroll
                for (int cc = 0; cc < 3; cc++)
                    p[r][cc] = s_in[c][2 * ly + r][2 * lx + cc];
#pragma unroll
            for (int co = 0; co < COT; co++) {
#pragma unroll
                for (int k = 0; k < 9; k++)
                    acc[co] = fmaf(p[k / 3][k % 3], s_w[c][co][k], acc[co]);
            }
        }
        __syncthreads();
    }

    const int oy = ty0 + ly, ox = tx0 + lx;
    if (oy < HO && ox < WO) {
#pragma unroll
        for (int co = 0; co < COT; co++) {
            float v = lrelu_f(acc[co] + bias[cob + co]);
            out[(((size_t)n * CO + cob + co) * HO + oy) * WO + ox] = v;
        }
    }
}

// ---------------------------------------------------------------------------
// Head: 3x3 conv, 8 -> 1 channels, 192x192.
// ---------------------------------------------------------------------------
__global__ void head_k(const float* __restrict__ x, const float* __restrict__ w,
                       const float* __restrict__ b, float* __restrict__ out)
{
    __shared__ float sw[72];
    __shared__ float sb;
    if (threadIdx.x < 72) sw[threadIdx.x] = w[threadIdx.x];
    if (threadIdx.x == 0) sb = b[0];
    __syncthreads();

    const int HW = 192 * 192;
    int idx = blockIdx.x * blockDim.x + threadIdx.x;
    if (idx >= 16 * HW) return;
    int n   = idx / HW;
    int rem = idx - n * HW;
    int y   = rem / 192;
    int xq  = rem - y * 192;

    float acc = sb;
#pragma unroll
    for (int ci = 0; ci < 8; ci++) {
        const float* xp = x + (size_t)(n * 8 + ci) * HW;
#pragma unroll
        for (int ky = 0; ky < 3; ky++) {
            int yy = y + ky - 1;
            if ((unsigned)yy >= 192u) continue;
#pragma unroll
            for (int kx = 0; kx < 3; kx++) {
                int xx = xq + kx - 1;
                if ((unsigned)xx >= 192u) continue;
                acc = fmaf(xp[yy * 192 + xx], sw[ci * 9 + ky * 3 + kx], acc);
            }
        }
    }
    out[idx] = acc;
}

// ---------------------------------------------------------------------------
// host
// ---------------------------------------------------------------------------
extern "C" void kernel_launch(void* const* d_in, const int* in_sizes, int n_in,
                              void* d_out, int out_size)
{
    const float* h1     = (const float*)d_in[0];
    const float* h2     = (const float*)d_in[1];
    const float* h3     = (const float*)d_in[2];
    const float* y_add  = (const float*)d_in[3];
    const float* enc_w1 = (const float*)d_in[4];
    const float* enc_b1 = (const float*)d_in[5];
    const float* enc_w2 = (const float*)d_in[6];
    const float* enc_b2 = (const float*)d_in[7];
    const float* enc_w3 = (const float*)d_in[8];
    const float* enc_b3 = (const float*)d_in[9];
    const float* g3wg   = (const float*)d_in[10];
    const float* g3bg   = (const float*)d_in[11];
    const float* g3wc   = (const float*)d_in[12];
    const float* g3bc   = (const float*)d_in[13];
    const float* g2wg   = (const float*)d_in[14];
    const float* g2bg   = (const float*)d_in[15];
    const float* g2wc   = (const float*)d_in[16];
    const float* g2bc   = (const float*)d_in[17];
    const float* g1wg   = (const float*)d_in[18];
    const float* g1bg   = (const float*)d_in[19];
    const float* g1wc   = (const float*)d_in[20];
    const float* g1bc   = (const float*)d_in[21];
    const float* s3w    = (const float*)d_in[22];
    const float* s3b    = (const float*)d_in[23];
    const float* s2w    = (const float*)d_in[24];
    const float* s2b    = (const float*)d_in[25];
    const float* s1w    = (const float*)d_in[26];
    const float* s1b    = (const float*)d_in[27];
    const float* hw     = (const float*)d_in[28];
    const float* hb     = (const float*)d_in[29];
    float* out = (float*)d_out;

    float *e1, *e2, *e3, *c3b, *c2b, *c1b, *gg3, *gg2, *gg1, *o3, *o2, *o1, *part;
    cudaGetSymbolAddress((void**)&e1, g_e1);
    cudaGetSymbolAddress((void**)&e2, g_e2);
    cudaGetSymbolAddress((void**)&e3, g_e3);
    cudaGetSymbolAddress((void**)&c3b, g_c3);
    cudaGetSymbolAddress((void**)&c2b, g_c2);
    cudaGetSymbolAddress((void**)&c1b, g_c1);
    cudaGetSymbolAddress((void**)&gg3, g_g3);
    cudaGetSymbolAddress((void**)&gg2, g_g2);
    cudaGetSymbolAddress((void**)&gg1, g_g1);
    cudaGetSymbolAddress((void**)&o3, g_o3);
    cudaGetSymbolAddress((void**)&o2, g_o2);
    cudaGetSymbolAddress((void**)&o1, g_o1);
    cudaGetSymbolAddress((void**)&part, g_part);

    const size_t SZ3 = (size_t)16 * 96 * 24 * 24;
    const size_t SZ2 = (size_t)16 * 64 * 48 * 48;
    const size_t SZ1 = (size_t)16 * 16 * 96 * 96;

    // -------- encoder over all 160 frames (transpose folded into enc1) -----
    conv3x3s2_k<1, 16, 192, true, 16, 16, 1, 16><<<dim3(36, 1, 160), 256>>>(
        y_add, enc_w1, enc_b1, e1);
    conv3x3s2_k<16, 64, 96, false, 16, 16, 8, 8><<<dim3(9, 8, 160), 256>>>(
        e1, enc_w2, enc_b2, e2);
    conv3x3s2_k<64, 96, 48, false, 16, 16, 8, 8><<<dim3(4, 12, 160), 256>>>(
        e2, enc_w3, enc_b3, e3);

    cudaMemcpyAsync(c3b, h3, SZ3 * sizeof(float), cudaMemcpyDeviceToDevice);
    cudaMemcpyAsync(c2b, h2, SZ2 * sizeof(float), cudaMemcpyDeviceToDevice);
    cudaMemcpyAsync(c1b, h1, SZ1 * sizeof(float), cudaMemcpyDeviceToDevice);

    for (int t = 0; t < 10; t++) {
        const float* x3 = e3 + (size_t)t * 16 * 96 * 24 * 24;
        float* c3c = c3b + (size_t)(t & 1) * SZ3;
        float* c3n = c3b + (size_t)((t + 1) & 1) * SZ3;
        float* c2c = c2b + (size_t)(t & 1) * SZ2;
        float* c2n = c2b + (size_t)((t + 1) & 1) * SZ2;
        float* c1c = c1b + (size_t)(t & 1) * SZ1;
        float* c1n = c1b + (size_t)((t + 1) & 1) * SZ1;

        // --- level 3 (24x24) ---
        conv3x3_v2<96, 96, 192, 24, 24, 2, 1, 24, 24, 1, 8, 8, 4>
            <<<dim3(1, 24, 64), 144>>>(x3, c3c, nullptr, g3wg, g3bg, part);
        epi_k<192, 576, 4, 1><<<1728, 256>>>(part, g3bg, nullptr, nullptr, gg3);
        conv3x3_v2<96, 96, 96, 24, 24, 1, 2, 24, 24, 1, 8, 8, 4>
            <<<dim3(1, 12, 64), 144>>>(x3, c3c, gg3, g3wc, g3bc, part);
        epi_k<96, 576, 4, 2><<<864, 256>>>(part, g3bc, gg3, c3c, c3n);
        deconv_v2<96, 64, 24, 24, 24, 8, 4, 2, 0>
            <<<dim3(1, 16, 32), 144>>>(c3n, s3w, s3b, part);
        epi_k<64, 2304, 2, 0><<<2304, 256>>>(part, s3b, nullptr, nullptr, o3);

        // --- level 2 (48x48) ---
        conv3x3_v2<64, 64, 128, 48, 48, 2, 1, 24, 48, 2, 4, 8, 2>
            <<<dim3(2, 16, 32), 144>>>(o3, c2c, nullptr, g2wg, g2bg, part);
        epi_k<128, 2304, 2, 1><<<4608, 256>>>(part, g2bg, nullptr, nullptr, gg2);
        conv3x3_v2<64, 64, 64, 48, 48, 1, 2, 24, 48, 2, 4, 8, 2>
            <<<dim3(2, 8, 32), 144>>>(o3, c2c, gg2, g2wc, g2bc, part);
        epi_k<64, 2304, 2, 2><<<2304, 256>>>(part, g2bc, gg2, c2c, c2n);
        deconv_v2<64, 16, 48, 16, 48, 8, 4, 2, 0>
            <<<dim3(3, 4, 32), 192>>>(c2n, s2w, s2b, part);
        epi_k<16, 9216, 2, 0><<<2304, 256>>>(part, s2b, nullptr, nullptr, o2);

        // --- level 1 (96x96) fused ---
        conv3x3_v2<16, 16, 32, 96, 96, 2, 1, 24, 48, 2, 4, 4, 1>
            <<<dim3(8, 8, 16), 144>>>(o2, c1c, nullptr, g1wg, g1bg, gg1);
        conv3x3_v2<16, 16, 16, 96, 96, 1, 2, 24, 48, 2, 4, 4, 1>
            <<<dim3(8, 4, 16), 144>>>(o2, c1c, gg1, g1wc, g1bc, c1n);
        deconv_v2<16, 8, 96, 16, 48, 4, 4, 1, 1>
            <<<dim3(12, 2, 16), 192>>>(c1n, s1w, s1b, o1);

        head_k<<<dim3((16 * 192 * 192 + 255) / 256), 256>>>(
            o1, hw, hb, out + (size_t)t * 16 * 192 * 192);
    }
}